// round 14
// baseline (speedup 1.0000x reference)
#include <cuda_runtime.h>
#include <cuda_fp16.h>
#include <mma.h>
#include <cstdint>

using namespace nvcuda;

#define NN 50000
#define NE 800000
#define H  64
#define REL 5
#define NB 196          // (NN + 255) / 256

// ---- device scratch (static globals; no runtime allocation) ----
// g_deg / g_cnt are SELF-RESTORING: zero at module load (.bss), re-zeroed by the
// tail of k_out_tc each call, so k_setup may accumulate into them immediately.
__device__ unsigned int g_zh[NN * 32];           // z as half2   (6.4 MB)
__device__ unsigned int g_yh[REL * NN * 32];     // y_r as half2 (32 MB)
__device__ unsigned int g_mh[NN * 32];           // m hi as half2
__device__ unsigned int g_ml[NN * 32];           // m lo as half2
__device__ int   g_deg[NN];              // col-degree (for gcn norm)
__device__ int   g_cnt[NN];              // row-degree (for sort)
__device__ int   g_off[NN + 1];          // CSR offsets by dst
__device__ int   g_cur[NN];              // scatter cursors
__device__ int   g_es[NE];               // sorted packed edges: src | type<<16
__device__ __half g_Ah[NN * H];          // risk hi split, fp16 (6.4 MB)
__device__ __half g_Al[NN * H];          // risk lo split, fp16
__device__ __half g_Wh[6 * H * H];       // combined weights, fp16 (single)
__device__ __half g_Woh[H * H];          // W_out hi split
__device__ __half g_Wol[H * H];          // W_out lo split
__device__ float g_BC[6 * H];            // [b | b@W_rel_r]

__device__ __forceinline__ void cp16(void* s, const void* g) {
    uint32_t sa = (uint32_t)__cvta_generic_to_shared(s);
    asm volatile("cp.async.ca.shared.global [%0], [%1], 16;" :: "r"(sa), "l"(g));
}
__device__ __forceinline__ void cp_commit_wait() {
    asm volatile("cp.async.commit_group;");
    asm volatile("cp.async.wait_group 0;" ::: "memory");
}

// ========== setup: fp16 splits (A, Wout) + combined weights + degrees ==========
__global__ void k_setup(const float* __restrict__ risk, const float* __restrict__ Wout,
                        const float* __restrict__ Win, const float* __restrict__ bin,
                        const float* __restrict__ Wrel, const int* __restrict__ ei) {
    int i = blockIdx.x * blockDim.x + threadIdx.x;
    int stride = gridDim.x * blockDim.x;

    // A hi/lo split
    for (int j = i; j < NN * 16; j += stride) {
        float4 v = ((const float4*)risk)[j];
        __half hx = __float2half_rn(v.x), hy = __float2half_rn(v.y);
        __half hz = __float2half_rn(v.z), hw = __float2half_rn(v.w);
        ((__half2*)g_Ah)[j * 2]     = __half2(hx, hy);
        ((__half2*)g_Ah)[j * 2 + 1] = __half2(hz, hw);
        ((__half2*)g_Al)[j * 2]     = __half2(
            __float2half_rn(v.x - __half2float(hx)),
            __float2half_rn(v.y - __half2float(hy)));
        ((__half2*)g_Al)[j * 2 + 1] = __half2(
            __float2half_rn(v.z - __half2float(hz)),
            __float2half_rn(v.w - __half2float(hw)));
    }
    // Wout hi/lo split
    for (int j = i; j < H * H; j += stride) {
        float v = Wout[j];
        __half hi = __float2half_rn(v);
        g_Woh[j] = hi;
        g_Wol[j] = __float2half_rn(v - __half2float(hi));
    }
    // combined weights: W[0]=W_in, W[1+r]=W_in@W_rel[r]; biases
    for (int idx = i; idx < 6 * H * H; idx += stride) {
        int m = idx >> 12, k = (idx >> 6) & 63, h = idx & 63;
        float s;
        if (m == 0) {
            s = Win[k * H + h];
            if (k == 0) g_BC[h] = bin[h];
        } else {
            const float* Wr = Wrel + (m - 1) * H * H;
            s = 0.f;
            #pragma unroll 8
            for (int j = 0; j < H; j++) s += Win[k * H + j] * Wr[j * H + h];
            if (k == 0) {
                float sb = 0.f;
                for (int j = 0; j < H; j++) sb += bin[j] * Wr[j * H + h];
                g_BC[m * H + h] = sb;
            }
        }
        g_Wh[idx] = __float2half_rn(s);
    }
    // degrees (g_deg/g_cnt pre-zeroed by tail of previous call / module load)
    for (int e = i; e < NE; e += stride) {
        atomicAdd(&g_deg[ei[NE + e]], 1);   // col-degree (norm)
        atomicAdd(&g_cnt[ei[e]], 1);        // row-degree (sort)
    }
}

// ================= tensor-core node GEMM (wmma fp16 split-2) =================
// Grid (391, 6): block = (node-tile of 128, matrix m). 8 warps; warp w owns 16 rows.
// D = Ah@B + Al@B, fp32 accumulate. Fills via cp.async.
#define LDAB 72      // fp16 leading dim (mult of 8 elems = 16B)
#define LDST 68      // float leading dim for staging
#define TCN_SMEM (2 * 128 * LDAB * 2 + 64 * LDAB * 2)   // 46080 B

__global__ void __launch_bounds__(256) k_node_tc() {
    extern __shared__ char smc[];
    __half* sAh = (__half*)smc;
    __half* sAl = sAh + 128 * LDAB;
    __half* sWh = sAl + 128 * LDAB;
    float*  sSt = (float*)smc;      // staging reuses A region (34.8KB < 36.9KB)

    int t = threadIdx.x;
    int w = t >> 5, lane = t & 31;
    int node0 = blockIdx.x * 128;
    int m = blockIdx.y;

    // A fill via cp.async: 2048 16B chunks (Ah, Al)
    for (int i = t; i < 2048; i += 256) {
        int arr = i >> 10;
        int rc = i & 1023;
        int r = rc >> 3, c8 = rc & 7;
        __half* sdst = (arr ? sAl : sAh) + r * LDAB + c8 * 8;
        if (node0 + r < NN) {
            const __half* gsrc = (arr ? g_Al : g_Ah) + (node0 + r) * 64 + c8 * 8;
            cp16(sdst, gsrc);
        } else {
            *(uint4*)sdst = make_uint4(0, 0, 0, 0);
        }
    }
    // W fill: 512 chunks
    for (int i = t; i < 512; i += 256) {
        int r = i >> 3, c8 = i & 7;
        cp16(sWh + r * LDAB + c8 * 8, g_Wh + m * 4096 + r * 64 + c8 * 8);
    }
    cp_commit_wait();
    __syncthreads();

    wmma::fragment<wmma::accumulator, 16, 16, 16, float> acc[4];
    #pragma unroll
    for (int n = 0; n < 4; n++) wmma::fill_fragment(acc[n], 0.f);

    #pragma unroll
    for (int k = 0; k < 4; k++) {
        wmma::fragment<wmma::matrix_a, 16, 16, 16, __half, wmma::row_major> ah, al;
        wmma::load_matrix_sync(ah, &sAh[(w * 16) * LDAB + k * 16], LDAB);
        wmma::load_matrix_sync(al, &sAl[(w * 16) * LDAB + k * 16], LDAB);
        #pragma unroll
        for (int n = 0; n < 4; n++) {
            wmma::fragment<wmma::matrix_b, 16, 16, 16, __half, wmma::row_major> bh;
            wmma::load_matrix_sync(bh, &sWh[(k * 16) * LDAB + n * 16], LDAB);
            wmma::mma_sync(acc[n], ah, bh, acc[n]);
            wmma::mma_sync(acc[n], al, bh, acc[n]);
        }
    }

    __syncthreads();   // all smem reads (A/W) complete before staging overwrites A
    float* st = sSt + (w * 16) * LDST;   // warp-private 16x68 staging
    #pragma unroll
    for (int n = 0; n < 4; n++)
        wmma::store_matrix_sync(st + n * 16, acc[n], LDST, wmma::mem_row_major);
    __syncwarp();

    for (int i = lane; i < 16 * 16; i += 32) {
        int rr = i >> 4, cgp = i & 15;
        int n = node0 + w * 16 + rr;
        if (n >= NN) continue;
        float4 v = *(float4*)&st[rr * LDST + cgp * 4];
        float4 b = ((const float4*)&g_BC[m * 64])[cgp];
        v.x += b.x; v.y += b.y; v.z += b.z; v.w += b.w;
        if (m == 0) {
            int dg = g_deg[n];
            float dis = dg > 0 ? rsqrtf((float)dg) : 0.f;
            v.x *= dis; v.y *= dis; v.z *= dis; v.w *= dis;
        }
        __half2 h0 = __floats2half2_rn(v.x, v.y);
        __half2 h1 = __floats2half2_rn(v.z, v.w);
        uint2 u = make_uint2(*(unsigned int*)&h0, *(unsigned int*)&h1);
        if (m == 0) ((uint2*)g_zh)[n * 16 + cgp] = u;
        else        ((uint2*)g_yh)[((m - 1) * NN + n) * 16 + cgp] = u;
    }
}

// ========== fused scan: chunk sums (warp-parallel) + scan + offsets ==========
__global__ void __launch_bounds__(256) k_scan() {
    __shared__ int csum[256];
    __shared__ int s[256];
    int t = threadIdx.x, w = t >> 5, l = t & 31;

    csum[t] = 0;
    __syncthreads();
    // phase A: each block redundantly computes all NB chunk sums (coalesced)
    for (int c = w; c < NB; c += 8) {
        int sum = 0;
        #pragma unroll
        for (int q = 0; q < 8; q++) {
            int idx = c * 256 + q * 32 + l;
            sum += (idx < NN) ? g_cnt[idx] : 0;
        }
        #pragma unroll
        for (int d = 16; d > 0; d >>= 1) sum += __shfl_down_sync(0xFFFFFFFFu, sum, d);
        if (l == 0) csum[c] = sum;
    }
    __syncthreads();
    // inclusive scan of chunk sums
    #pragma unroll
    for (int d = 1; d < 256; d <<= 1) {
        int u = (t >= d) ? csum[t - d] : 0;
        __syncthreads();
        csum[t] += u;
        __syncthreads();
    }
    // phase B: local scan of this block's chunk
    int b = blockIdx.x;
    int idx = b * 256 + t;
    int v = idx < NN ? g_cnt[idx] : 0;
    s[t] = v;
    __syncthreads();
    #pragma unroll
    for (int d = 1; d < 256; d <<= 1) {
        int u = (t >= d) ? s[t - d] : 0;
        __syncthreads();
        s[t] += u;
        __syncthreads();
    }
    int boff = b > 0 ? csum[b - 1] : 0;
    int excl = s[t] - v + boff;
    if (idx < NN) { g_off[idx] = excl; g_cur[idx] = excl; }
    if (idx == NN - 1) g_off[NN] = NE;
}

__global__ void k_scatter(const int* __restrict__ ei, const int* __restrict__ et) {
    int e = blockIdx.x * blockDim.x + threadIdx.x;
    if (e >= NE) return;
    int r = ei[e], c = ei[NE + e], tp = et[e];
    int pos = atomicAdd(&g_cur[r], 1);
    g_es[pos] = c | (tp << 16);
}

// ================= sorted edge pass =================
// One warp per dst node; 4 independent accumulator chains for MLP.
// Emits m as fp16 hi/lo for the wmma output GEMM.
__global__ void __launch_bounds__(256) k_edge2() {
    int t = threadIdx.x;
    int node = blockIdx.x * 8 + (t >> 5);
    if (node >= NN) return;
    int l = t & 31;
    int beg = g_off[node], end = g_off[node + 1];

    float2 gcn[4], ss[4], nm[4];
    #pragma unroll
    for (int q = 0; q < 4; q++) {
        gcn[q] = make_float2(0.f, 0.f);
        ss[q]  = make_float2(0.f, 0.f);
        nm[q]  = make_float2(0.f, 0.f);
    }

    int i = beg;
    for (; i + 3 < end; i += 4) {
        int pk[4];
        #pragma unroll
        for (int q = 0; q < 4; q++) pk[q] = __ldg(&g_es[i + q]);
        unsigned int zu[4], yu[4];
        #pragma unroll
        for (int q = 0; q < 4; q++) {
            int c = pk[q] & 0xFFFF, tp = pk[q] >> 16;
            zu[q] = __ldg(&g_zh[c * 32 + l]);
            yu[q] = __ldg(&g_yh[(tp * NN + c) * 32 + l]);
        }
        #pragma unroll
        for (int q = 0; q < 4; q++) {
            float2 zv = __half22float2(*(__half2*)&zu[q]);
            float2 yv = __half22float2(*(__half2*)&yu[q]);
            float ex = __expf(yv.x), ey = __expf(yv.y);
            gcn[q].x += zv.x;       gcn[q].y += zv.y;
            ss[q].x  += ex;         ss[q].y  += ey;
            nm[q].x  += yv.x * ex;  nm[q].y  += yv.y * ey;
        }
    }
    for (; i < end; i++) {
        int pk = __ldg(&g_es[i]);
        int c = pk & 0xFFFF, tp = pk >> 16;
        unsigned int zu = __ldg(&g_zh[c * 32 + l]);
        unsigned int yu = __ldg(&g_yh[(tp * NN + c) * 32 + l]);
        float2 zv = __half22float2(*(__half2*)&zu);
        float2 yv = __half22float2(*(__half2*)&yu);
        float ex = __expf(yv.x), ey = __expf(yv.y);
        gcn[0].x += zv.x;       gcn[0].y += zv.y;
        ss[0].x  += ex;         ss[0].y  += ey;
        nm[0].x  += yv.x * ex;  nm[0].y  += yv.y * ey;
    }

    float2 G = make_float2(gcn[0].x + gcn[1].x + gcn[2].x + gcn[3].x,
                           gcn[0].y + gcn[1].y + gcn[2].y + gcn[3].y);
    float2 S = make_float2(ss[0].x + ss[1].x + ss[2].x + ss[3].x,
                           ss[0].y + ss[1].y + ss[2].y + ss[3].y);
    float2 U = make_float2(nm[0].x + nm[1].x + nm[2].x + nm[3].x,
                           nm[0].y + nm[1].y + nm[2].y + nm[3].y);

    int dg = g_deg[node];
    float dis = dg > 0 ? rsqrtf((float)dg) : 0.f;
    float2 m;
    m.x = dis * G.x + 0.5f * fmaxf(U.x / (S.x + 1e-16f), 0.f);
    m.y = dis * G.y + 0.5f * fmaxf(U.y / (S.y + 1e-16f), 0.f);

    __half2 mh = __floats2half2_rn(m.x, m.y);
    float2 mhf = __half22float2(mh);
    __half2 ml = __floats2half2_rn(m.x - mhf.x, m.y - mhf.y);
    g_mh[node * 32 + l] = *(unsigned int*)&mh;
    g_ml[node * 32 + l] = *(unsigned int*)&ml;
}

// ================= output GEMM (wmma, 3-term split) =================
// Grid 391: 128 nodes/block, 8 warps. D = Mh@Woh + Ml@Woh + Mh@Wol.
// Tail: zero g_deg/g_cnt for the next call (self-restoring state).
#define KOUT_SMEM (2 * 128 * LDAB * 2 + 2 * 64 * LDAB * 2)   // 55296 B

__global__ void __launch_bounds__(256) k_out_tc(const float* __restrict__ bout,
                                                float* __restrict__ out) {
    extern __shared__ char smc[];
    __half* sMh = (__half*)smc;
    __half* sMl = sMh + 128 * LDAB;
    __half* sWh = sMl + 128 * LDAB;
    __half* sWl = sWh + 64 * LDAB;
    float*  sSt = (float*)smc;

    int t = threadIdx.x;
    int w = t >> 5, lane = t & 31;
    int node0 = blockIdx.x * 128;

    for (int i = t; i < 2048; i += 256) {
        int arr = i >> 10;
        int rc = i & 1023;
        int r = rc >> 3, c8 = rc & 7;
        __half* sdst = (arr ? sMl : sMh) + r * LDAB + c8 * 8;
        if (node0 + r < NN) {
            const __half* gsrc = (const __half*)(arr ? g_ml : g_mh) + (node0 + r) * 64 + c8 * 8;
            cp16(sdst, gsrc);
        } else {
            *(uint4*)sdst = make_uint4(0, 0, 0, 0);
        }
    }
    for (int i = t; i < 1024; i += 256) {
        int arr = i >> 9;
        int rc = i & 511;
        int r = rc >> 3, c8 = rc & 7;
        __half* sdst = (arr ? sWl : sWh) + r * LDAB + c8 * 8;
        const __half* gsrc = (arr ? g_Wol : g_Woh) + r * 64 + c8 * 8;
        cp16(sdst, gsrc);
    }

    // tail-zero degree arrays for the next call (overlaps with cp.async)
    int gid = blockIdx.x * 256 + t;
    if (gid < NN) { g_deg[gid] = 0; g_cnt[gid] = 0; }

    cp_commit_wait();
    __syncthreads();

    wmma::fragment<wmma::accumulator, 16, 16, 16, float> acc[4];
    #pragma unroll
    for (int n = 0; n < 4; n++) wmma::fill_fragment(acc[n], 0.f);

    #pragma unroll
    for (int k = 0; k < 4; k++) {
        wmma::fragment<wmma::matrix_a, 16, 16, 16, __half, wmma::row_major> ah, al;
        wmma::load_matrix_sync(ah, &sMh[(w * 16) * LDAB + k * 16], LDAB);
        wmma::load_matrix_sync(al, &sMl[(w * 16) * LDAB + k * 16], LDAB);
        #pragma unroll
        for (int n = 0; n < 4; n++) {
            wmma::fragment<wmma::matrix_b, 16, 16, 16, __half, wmma::row_major> bh, bl;
            wmma::load_matrix_sync(bh, &sWh[(k * 16) * LDAB + n * 16], LDAB);
            wmma::load_matrix_sync(bl, &sWl[(k * 16) * LDAB + n * 16], LDAB);
            wmma::mma_sync(acc[n], ah, bh, acc[n]);
            wmma::mma_sync(acc[n], al, bh, acc[n]);
            wmma::mma_sync(acc[n], ah, bl, acc[n]);
        }
    }

    __syncthreads();
    float* st = sSt + (w * 16) * LDST;
    #pragma unroll
    for (int n = 0; n < 4; n++)
        wmma::store_matrix_sync(st + n * 16, acc[n], LDST, wmma::mem_row_major);
    __syncwarp();

    for (int i = lane; i < 16 * 16; i += 32) {
        int rr = i >> 4, cgp = i & 15;
        int n = node0 + w * 16 + rr;
        if (n >= NN) continue;
        float4 v = *(float4*)&st[rr * LDST + cgp * 4];
        float4 b = __ldg(&((const float4*)bout)[cgp]);
        v.x += b.x; v.y += b.y; v.z += b.z; v.w += b.w;
        ((float4*)out)[n * 16 + cgp] = v;
    }
}

extern "C" void kernel_launch(void* const* d_in, const int* in_sizes, int n_in,
                              void* d_out, int out_size) {
    const float* risk = (const float*)d_in[0];
    // d_in[1] = edge_weight (unused by the reference)
    const float* Win  = (const float*)d_in[2];
    const float* bin  = (const float*)d_in[3];
    const float* Wrel = (const float*)d_in[4];
    const float* Wout = (const float*)d_in[5];
    const float* bout = (const float*)d_in[6];
    const int*   ei   = (const int*)d_in[7];   // [2, NE]: row (dst), col (src)
    const int*   et   = (const int*)d_in[8];
    float* out = (float*)d_out;

    cudaFuncSetAttribute(k_node_tc, cudaFuncAttributeMaxDynamicSharedMemorySize, TCN_SMEM);
    cudaFuncSetAttribute(k_out_tc,  cudaFuncAttributeMaxDynamicSharedMemorySize, KOUT_SMEM);

    // 6 launches; the ncu capture profiles launch #4 = k_scatter this round.
    k_setup<<<512, 256>>>(risk, Wout, Win, bin, Wrel, ei);
    k_node_tc<<<dim3((NN + 127) / 128, 6), 256, TCN_SMEM>>>();
    k_scan<<<NB, 256>>>();
    k_scatter<<<(NE + 255) / 256, 256>>>(ei, et);
    k_edge2<<<(NN + 7) / 8, 256>>>();
    k_out_tc<<<(NN + 127) / 128, 256, KOUT_SMEM>>>(bout, out);
}

// round 15
// speedup vs baseline: 1.0092x; 1.0092x over previous
#include <cuda_runtime.h>
#include <cuda_fp16.h>
#include <mma.h>
#include <cstdint>

using namespace nvcuda;

#define NN 50000
#define NE 800000
#define H  64
#define REL 5
#define NB 196          // (NN + 255) / 256

// ---- device scratch (static globals; no runtime allocation) ----
// g_deg / g_cnt are SELF-RESTORING: zero at module load (.bss), re-zeroed by the
// tail of k_out_tc each call, so k_setup may accumulate into them immediately.
__device__ unsigned int g_zy[NN * 6 * 32];       // [node][m][lane] half2: m=0 is z, m=1+tp is y (38.4MB)
__device__ unsigned int g_mh[NN * 32];           // m hi as half2
__device__ unsigned int g_ml[NN * 32];           // m lo as half2
__device__ int   g_deg[NN];              // col-degree (for gcn norm)
__device__ int   g_cnt[NN];              // row-degree (for sort)
__device__ int   g_off[NN + 1];          // CSR offsets by dst
__device__ int   g_cur[NN];              // scatter cursors
__device__ int   g_es[NE];               // sorted packed edges: src | type<<16
__device__ __half g_Ah[NN * H];          // risk hi split, fp16 (6.4 MB)
__device__ __half g_Al[NN * H];          // risk lo split, fp16
__device__ __half g_Wh[6 * H * H];       // combined weights, fp16 (single)
__device__ __half g_Woh[H * H];          // W_out hi split
__device__ __half g_Wol[H * H];          // W_out lo split
__device__ float g_BC[6 * H];            // [b | b@W_rel_r]

__device__ __forceinline__ void cp16(void* s, const void* g) {
    uint32_t sa = (uint32_t)__cvta_generic_to_shared(s);
    asm volatile("cp.async.ca.shared.global [%0], [%1], 16;" :: "r"(sa), "l"(g));
}
__device__ __forceinline__ void cp_commit_wait() {
    asm volatile("cp.async.commit_group;");
    asm volatile("cp.async.wait_group 0;" ::: "memory");
}

// ========== setup: fp16 splits (A, Wout) + combined weights + degrees ==========
__global__ void k_setup(const float* __restrict__ risk, const float* __restrict__ Wout,
                        const float* __restrict__ Win, const float* __restrict__ bin,
                        const float* __restrict__ Wrel, const int* __restrict__ ei) {
    int i = blockIdx.x * blockDim.x + threadIdx.x;
    int stride = gridDim.x * blockDim.x;

    // A hi/lo split
    for (int j = i; j < NN * 16; j += stride) {
        float4 v = ((const float4*)risk)[j];
        __half hx = __float2half_rn(v.x), hy = __float2half_rn(v.y);
        __half hz = __float2half_rn(v.z), hw = __float2half_rn(v.w);
        ((__half2*)g_Ah)[j * 2]     = __half2(hx, hy);
        ((__half2*)g_Ah)[j * 2 + 1] = __half2(hz, hw);
        ((__half2*)g_Al)[j * 2]     = __half2(
            __float2half_rn(v.x - __half2float(hx)),
            __float2half_rn(v.y - __half2float(hy)));
        ((__half2*)g_Al)[j * 2 + 1] = __half2(
            __float2half_rn(v.z - __half2float(hz)),
            __float2half_rn(v.w - __half2float(hw)));
    }
    // Wout hi/lo split
    for (int j = i; j < H * H; j += stride) {
        float v = Wout[j];
        __half hi = __float2half_rn(v);
        g_Woh[j] = hi;
        g_Wol[j] = __float2half_rn(v - __half2float(hi));
    }
    // combined weights: W[0]=W_in, W[1+r]=W_in@W_rel[r]; biases
    for (int idx = i; idx < 6 * H * H; idx += stride) {
        int m = idx >> 12, k = (idx >> 6) & 63, h = idx & 63;
        float s;
        if (m == 0) {
            s = Win[k * H + h];
            if (k == 0) g_BC[h] = bin[h];
        } else {
            const float* Wr = Wrel + (m - 1) * H * H;
            s = 0.f;
            #pragma unroll 8
            for (int j = 0; j < H; j++) s += Win[k * H + j] * Wr[j * H + h];
            if (k == 0) {
                float sb = 0.f;
                for (int j = 0; j < H; j++) sb += bin[j] * Wr[j * H + h];
                g_BC[m * H + h] = sb;
            }
        }
        g_Wh[idx] = __float2half_rn(s);
    }
    // degrees (g_deg/g_cnt pre-zeroed by tail of previous call / module load)
    for (int e = i; e < NE; e += stride) {
        atomicAdd(&g_deg[ei[NE + e]], 1);   // col-degree (norm)
        atomicAdd(&g_cnt[ei[e]], 1);        // row-degree (sort)
    }
}

// ================= tensor-core node GEMM (wmma fp16 split-2) =================
// Grid (391, 6): block = (node-tile of 128, matrix m). 8 warps; warp w owns 16 rows.
// D = Ah@B + Al@B, fp32 accumulate. Fills via cp.async. Output -> g_zy[node][m][lane].
#define LDAB 72      // fp16 leading dim (mult of 8 elems = 16B)
#define LDST 68      // float leading dim for staging
#define TCN_SMEM (2 * 128 * LDAB * 2 + 64 * LDAB * 2)   // 46080 B

__global__ void __launch_bounds__(256) k_node_tc() {
    extern __shared__ char smc[];
    __half* sAh = (__half*)smc;
    __half* sAl = sAh + 128 * LDAB;
    __half* sWh = sAl + 128 * LDAB;
    float*  sSt = (float*)smc;      // staging reuses A region (34.8KB < 36.9KB)

    int t = threadIdx.x;
    int w = t >> 5, lane = t & 31;
    int node0 = blockIdx.x * 128;
    int m = blockIdx.y;

    // A fill via cp.async: 2048 16B chunks (Ah, Al)
    for (int i = t; i < 2048; i += 256) {
        int arr = i >> 10;
        int rc = i & 1023;
        int r = rc >> 3, c8 = rc & 7;
        __half* sdst = (arr ? sAl : sAh) + r * LDAB + c8 * 8;
        if (node0 + r < NN) {
            const __half* gsrc = (arr ? g_Al : g_Ah) + (node0 + r) * 64 + c8 * 8;
            cp16(sdst, gsrc);
        } else {
            *(uint4*)sdst = make_uint4(0, 0, 0, 0);
        }
    }
    // W fill: 512 chunks
    for (int i = t; i < 512; i += 256) {
        int r = i >> 3, c8 = i & 7;
        cp16(sWh + r * LDAB + c8 * 8, g_Wh + m * 4096 + r * 64 + c8 * 8);
    }
    cp_commit_wait();
    __syncthreads();

    wmma::fragment<wmma::accumulator, 16, 16, 16, float> acc[4];
    #pragma unroll
    for (int n = 0; n < 4; n++) wmma::fill_fragment(acc[n], 0.f);

    #pragma unroll
    for (int k = 0; k < 4; k++) {
        wmma::fragment<wmma::matrix_a, 16, 16, 16, __half, wmma::row_major> ah, al;
        wmma::load_matrix_sync(ah, &sAh[(w * 16) * LDAB + k * 16], LDAB);
        wmma::load_matrix_sync(al, &sAl[(w * 16) * LDAB + k * 16], LDAB);
        #pragma unroll
        for (int n = 0; n < 4; n++) {
            wmma::fragment<wmma::matrix_b, 16, 16, 16, __half, wmma::row_major> bh;
            wmma::load_matrix_sync(bh, &sWh[(k * 16) * LDAB + n * 16], LDAB);
            wmma::mma_sync(acc[n], ah, bh, acc[n]);
            wmma::mma_sync(acc[n], al, bh, acc[n]);
        }
    }

    __syncthreads();   // all smem reads (A/W) complete before staging overwrites A
    float* st = sSt + (w * 16) * LDST;   // warp-private 16x68 staging
    #pragma unroll
    for (int n = 0; n < 4; n++)
        wmma::store_matrix_sync(st + n * 16, acc[n], LDST, wmma::mem_row_major);
    __syncwarp();

    for (int i = lane; i < 16 * 16; i += 32) {
        int rr = i >> 4, cgp = i & 15;
        int n = node0 + w * 16 + rr;
        if (n >= NN) continue;
        float4 v = *(float4*)&st[rr * LDST + cgp * 4];
        float4 b = ((const float4*)&g_BC[m * 64])[cgp];
        v.x += b.x; v.y += b.y; v.z += b.z; v.w += b.w;
        if (m == 0) {
            int dg = g_deg[n];
            float dis = dg > 0 ? rsqrtf((float)dg) : 0.f;
            v.x *= dis; v.y *= dis; v.z *= dis; v.w *= dis;
        }
        __half2 h0 = __floats2half2_rn(v.x, v.y);
        __half2 h1 = __floats2half2_rn(v.z, v.w);
        uint2 u = make_uint2(*(unsigned int*)&h0, *(unsigned int*)&h1);
        ((uint2*)g_zy)[(n * 6 + m) * 16 + cgp] = u;
    }
}

// ========== fused scan: chunk sums (warp-parallel) + scan + offsets ==========
__global__ void __launch_bounds__(256) k_scan() {
    __shared__ int csum[256];
    __shared__ int s[256];
    int t = threadIdx.x, w = t >> 5, l = t & 31;

    csum[t] = 0;
    __syncthreads();
    // phase A: each block redundantly computes all NB chunk sums (coalesced)
    for (int c = w; c < NB; c += 8) {
        int sum = 0;
        #pragma unroll
        for (int q = 0; q < 8; q++) {
            int idx = c * 256 + q * 32 + l;
            sum += (idx < NN) ? g_cnt[idx] : 0;
        }
        #pragma unroll
        for (int d = 16; d > 0; d >>= 1) sum += __shfl_down_sync(0xFFFFFFFFu, sum, d);
        if (l == 0) csum[c] = sum;
    }
    __syncthreads();
    // inclusive scan of chunk sums
    #pragma unroll
    for (int d = 1; d < 256; d <<= 1) {
        int u = (t >= d) ? csum[t - d] : 0;
        __syncthreads();
        csum[t] += u;
        __syncthreads();
    }
    // phase B: local scan of this block's chunk
    int b = blockIdx.x;
    int idx = b * 256 + t;
    int v = idx < NN ? g_cnt[idx] : 0;
    s[t] = v;
    __syncthreads();
    #pragma unroll
    for (int d = 1; d < 256; d <<= 1) {
        int u = (t >= d) ? s[t - d] : 0;
        __syncthreads();
        s[t] += u;
        __syncthreads();
    }
    int boff = b > 0 ? csum[b - 1] : 0;
    int excl = s[t] - v + boff;
    if (idx < NN) { g_off[idx] = excl; g_cur[idx] = excl; }
    if (idx == NN - 1) g_off[NN] = NE;
}

// Scatter with 4-edge ILP: 4 independent load->atomic->store chains per thread.
__global__ void __launch_bounds__(256) k_scatter(const int* __restrict__ ei,
                                                 const int* __restrict__ et) {
    int base = blockIdx.x * 1024 + threadIdx.x;
    int r[4], c[4], tp[4], pos[4];
    bool ok[4];
    #pragma unroll
    for (int q = 0; q < 4; q++) {
        int e = base + 256 * q;
        ok[q] = e < NE;
        if (ok[q]) {
            r[q]  = __ldg(&ei[e]);
            c[q]  = __ldg(&ei[NE + e]);
            tp[q] = __ldg(&et[e]);
        }
    }
    #pragma unroll
    for (int q = 0; q < 4; q++)
        if (ok[q]) pos[q] = atomicAdd(&g_cur[r[q]], 1);
    #pragma unroll
    for (int q = 0; q < 4; q++)
        if (ok[q]) g_es[pos[q]] = c[q] | (tp[q] << 16);
}

// ================= sorted edge pass =================
// One warp per dst node; 4 independent accumulator chains for MLP.
// Gathers from node-major g_zy (z and y of one src node are 768B-local).
__global__ void __launch_bounds__(256) k_edge2() {
    int t = threadIdx.x;
    int node = blockIdx.x * 8 + (t >> 5);
    if (node >= NN) return;
    int l = t & 31;
    int beg = g_off[node], end = g_off[node + 1];

    float2 gcn[4], ss[4], nm[4];
    #pragma unroll
    for (int q = 0; q < 4; q++) {
        gcn[q] = make_float2(0.f, 0.f);
        ss[q]  = make_float2(0.f, 0.f);
        nm[q]  = make_float2(0.f, 0.f);
    }

    int i = beg;
    for (; i + 3 < end; i += 4) {
        int pk[4];
        #pragma unroll
        for (int q = 0; q < 4; q++) pk[q] = __ldg(&g_es[i + q]);
        unsigned int zu[4], yu[4];
        #pragma unroll
        for (int q = 0; q < 4; q++) {
            int c = pk[q] & 0xFFFF, tp = pk[q] >> 16;
            int base6 = c * 192 + l;
            zu[q] = __ldg(&g_zy[base6]);
            yu[q] = __ldg(&g_zy[base6 + (tp + 1) * 32]);
        }
        #pragma unroll
        for (int q = 0; q < 4; q++) {
            float2 zv = __half22float2(*(__half2*)&zu[q]);
            float2 yv = __half22float2(*(__half2*)&yu[q]);
            float ex = __expf(yv.x), ey = __expf(yv.y);
            gcn[q].x += zv.x;       gcn[q].y += zv.y;
            ss[q].x  += ex;         ss[q].y  += ey;
            nm[q].x  += yv.x * ex;  nm[q].y  += yv.y * ey;
        }
    }
    for (; i < end; i++) {
        int pk = __ldg(&g_es[i]);
        int c = pk & 0xFFFF, tp = pk >> 16;
        int base6 = c * 192 + l;
        unsigned int zu = __ldg(&g_zy[base6]);
        unsigned int yu = __ldg(&g_zy[base6 + (tp + 1) * 32]);
        float2 zv = __half22float2(*(__half2*)&zu);
        float2 yv = __half22float2(*(__half2*)&yu);
        float ex = __expf(yv.x), ey = __expf(yv.y);
        gcn[0].x += zv.x;       gcn[0].y += zv.y;
        ss[0].x  += ex;         ss[0].y  += ey;
        nm[0].x  += yv.x * ex;  nm[0].y  += yv.y * ey;
    }

    float2 G = make_float2(gcn[0].x + gcn[1].x + gcn[2].x + gcn[3].x,
                           gcn[0].y + gcn[1].y + gcn[2].y + gcn[3].y);
    float2 S = make_float2(ss[0].x + ss[1].x + ss[2].x + ss[3].x,
                           ss[0].y + ss[1].y + ss[2].y + ss[3].y);
    float2 U = make_float2(nm[0].x + nm[1].x + nm[2].x + nm[3].x,
                           nm[0].y + nm[1].y + nm[2].y + nm[3].y);

    int dg = g_deg[node];
    float dis = dg > 0 ? rsqrtf((float)dg) : 0.f;
    float2 m;
    m.x = dis * G.x + 0.5f * fmaxf(U.x / (S.x + 1e-16f), 0.f);
    m.y = dis * G.y + 0.5f * fmaxf(U.y / (S.y + 1e-16f), 0.f);

    __half2 mh = __floats2half2_rn(m.x, m.y);
    float2 mhf = __half22float2(mh);
    __half2 ml = __floats2half2_rn(m.x - mhf.x, m.y - mhf.y);
    g_mh[node * 32 + l] = *(unsigned int*)&mh;
    g_ml[node * 32 + l] = *(unsigned int*)&ml;
}

// ================= output GEMM (wmma, 3-term split) =================
// Grid 391: 128 nodes/block, 8 warps. D = Mh@Woh + Ml@Woh + Mh@Wol.
// Tail: zero g_deg/g_cnt for the next call (self-restoring state).
#define KOUT_SMEM (2 * 128 * LDAB * 2 + 2 * 64 * LDAB * 2)   // 55296 B

__global__ void __launch_bounds__(256) k_out_tc(const float* __restrict__ bout,
                                                float* __restrict__ out) {
    extern __shared__ char smc[];
    __half* sMh = (__half*)smc;
    __half* sMl = sMh + 128 * LDAB;
    __half* sWh = sMl + 128 * LDAB;
    __half* sWl = sWh + 64 * LDAB;
    float*  sSt = (float*)smc;

    int t = threadIdx.x;
    int w = t >> 5, lane = t & 31;
    int node0 = blockIdx.x * 128;

    for (int i = t; i < 2048; i += 256) {
        int arr = i >> 10;
        int rc = i & 1023;
        int r = rc >> 3, c8 = rc & 7;
        __half* sdst = (arr ? sMl : sMh) + r * LDAB + c8 * 8;
        if (node0 + r < NN) {
            const __half* gsrc = (const __half*)(arr ? g_ml : g_mh) + (node0 + r) * 64 + c8 * 8;
            cp16(sdst, gsrc);
        } else {
            *(uint4*)sdst = make_uint4(0, 0, 0, 0);
        }
    }
    for (int i = t; i < 1024; i += 256) {
        int arr = i >> 9;
        int rc = i & 511;
        int r = rc >> 3, c8 = rc & 7;
        __half* sdst = (arr ? sWl : sWh) + r * LDAB + c8 * 8;
        const __half* gsrc = (arr ? g_Wol : g_Woh) + r * 64 + c8 * 8;
        cp16(sdst, gsrc);
    }

    // tail-zero degree arrays for the next call (overlaps with cp.async)
    int gid = blockIdx.x * 256 + t;
    if (gid < NN) { g_deg[gid] = 0; g_cnt[gid] = 0; }

    cp_commit_wait();
    __syncthreads();

    wmma::fragment<wmma::accumulator, 16, 16, 16, float> acc[4];
    #pragma unroll
    for (int n = 0; n < 4; n++) wmma::fill_fragment(acc[n], 0.f);

    #pragma unroll
    for (int k = 0; k < 4; k++) {
        wmma::fragment<wmma::matrix_a, 16, 16, 16, __half, wmma::row_major> ah, al;
        wmma::load_matrix_sync(ah, &sMh[(w * 16) * LDAB + k * 16], LDAB);
        wmma::load_matrix_sync(al, &sMl[(w * 16) * LDAB + k * 16], LDAB);
        #pragma unroll
        for (int n = 0; n < 4; n++) {
            wmma::fragment<wmma::matrix_b, 16, 16, 16, __half, wmma::row_major> bh, bl;
            wmma::load_matrix_sync(bh, &sWh[(k * 16) * LDAB + n * 16], LDAB);
            wmma::load_matrix_sync(bl, &sWl[(k * 16) * LDAB + n * 16], LDAB);
            wmma::mma_sync(acc[n], ah, bh, acc[n]);
            wmma::mma_sync(acc[n], al, bh, acc[n]);
            wmma::mma_sync(acc[n], ah, bl, acc[n]);
        }
    }

    __syncthreads();
    float* st = sSt + (w * 16) * LDST;
    #pragma unroll
    for (int n = 0; n < 4; n++)
        wmma::store_matrix_sync(st + n * 16, acc[n], LDST, wmma::mem_row_major);
    __syncwarp();

    for (int i = lane; i < 16 * 16; i += 32) {
        int rr = i >> 4, cgp = i & 15;
        int n = node0 + w * 16 + rr;
        if (n >= NN) continue;
        float4 v = *(float4*)&st[rr * LDST + cgp * 4];
        float4 b = __ldg(&((const float4*)bout)[cgp]);
        v.x += b.x; v.y += b.y; v.z += b.z; v.w += b.w;
        ((float4*)out)[n * 16 + cgp] = v;
    }
}

extern "C" void kernel_launch(void* const* d_in, const int* in_sizes, int n_in,
                              void* d_out, int out_size) {
    const float* risk = (const float*)d_in[0];
    // d_in[1] = edge_weight (unused by the reference)
    const float* Win  = (const float*)d_in[2];
    const float* bin  = (const float*)d_in[3];
    const float* Wrel = (const float*)d_in[4];
    const float* Wout = (const float*)d_in[5];
    const float* bout = (const float*)d_in[6];
    const int*   ei   = (const int*)d_in[7];   // [2, NE]: row (dst), col (src)
    const int*   et   = (const int*)d_in[8];
    float* out = (float*)d_out;

    cudaFuncSetAttribute(k_node_tc, cudaFuncAttributeMaxDynamicSharedMemorySize, TCN_SMEM);
    cudaFuncSetAttribute(k_out_tc,  cudaFuncAttributeMaxDynamicSharedMemorySize, KOUT_SMEM);

    // 6 launches; the ncu capture profiles launch #4 = k_scatter this round.
    k_setup<<<512, 256>>>(risk, Wout, Win, bin, Wrel, ei);
    k_node_tc<<<dim3((NN + 127) / 128, 6), 256, TCN_SMEM>>>();
    k_scan<<<NB, 256>>>();
    k_scatter<<<(NE + 1023) / 1024, 256>>>(ei, et);
    k_edge2<<<(NN + 7) / 8, 256>>>();
    k_out_tc<<<(NN + 127) / 128, 256, KOUT_SMEM>>>(bout, out);
}

// round 16
// speedup vs baseline: 1.0298x; 1.0205x over previous
#include <cuda_runtime.h>
#include <cuda_fp16.h>
#include <mma.h>
#include <cstdint>

using namespace nvcuda;

#define NN 50000
#define NE 800000
#define H  64
#define REL 5
#define NB 196          // (NN + 255) / 256

// ---- device scratch (static globals; no runtime allocation) ----
// g_deg / g_cnt are SELF-RESTORING: zero at module load (.bss), re-zeroed by the
// tail of k_out_tc each call, so k_setup may accumulate into them immediately.
__device__ unsigned int g_zy[NN * 6 * 32];       // [node][m][lane] half2: m=0 is z, m=1+tp is y (38.4MB)
__device__ unsigned int g_mh[NN * 32];           // m hi as half2
__device__ unsigned int g_ml[NN * 32];           // m lo as half2
__device__ int   g_deg[NN];              // col-degree (for gcn norm)
__device__ int   g_cnt[NN];              // row-degree (for sort)
__device__ int   g_off[NN + 1];          // CSR offsets by dst
__device__ int   g_rank[NE];             // rank of edge within its dst group
__device__ int   g_es[NE];               // sorted packed edges: src | type<<16
__device__ __half g_Ah[NN * H];          // risk hi split, fp16 (6.4 MB)
__device__ __half g_Al[NN * H];          // risk lo split, fp16
__device__ __half g_Wh[6 * H * H];       // combined weights, fp16 (single)
__device__ __half g_Woh[H * H];          // W_out hi split
__device__ __half g_Wol[H * H];          // W_out lo split
__device__ float g_BC[6 * H];            // [b | b@W_rel_r]

__device__ __forceinline__ void cp16(void* s, const void* g) {
    uint32_t sa = (uint32_t)__cvta_generic_to_shared(s);
    asm volatile("cp.async.ca.shared.global [%0], [%1], 16;" :: "r"(sa), "l"(g));
}
__device__ __forceinline__ void cp_commit_wait() {
    asm volatile("cp.async.commit_group;");
    asm volatile("cp.async.wait_group 0;" ::: "memory");
}

// ========== setup: fp16 splits (A, Wout) + combined weights + degrees+ranks ==========
__global__ void k_setup(const float* __restrict__ risk, const float* __restrict__ Wout,
                        const float* __restrict__ Win, const float* __restrict__ bin,
                        const float* __restrict__ Wrel, const int* __restrict__ ei) {
    int i = blockIdx.x * blockDim.x + threadIdx.x;
    int stride = gridDim.x * blockDim.x;

    // A hi/lo split
    for (int j = i; j < NN * 16; j += stride) {
        float4 v = ((const float4*)risk)[j];
        __half hx = __float2half_rn(v.x), hy = __float2half_rn(v.y);
        __half hz = __float2half_rn(v.z), hw = __float2half_rn(v.w);
        ((__half2*)g_Ah)[j * 2]     = __half2(hx, hy);
        ((__half2*)g_Ah)[j * 2 + 1] = __half2(hz, hw);
        ((__half2*)g_Al)[j * 2]     = __half2(
            __float2half_rn(v.x - __half2float(hx)),
            __float2half_rn(v.y - __half2float(hy)));
        ((__half2*)g_Al)[j * 2 + 1] = __half2(
            __float2half_rn(v.z - __half2float(hz)),
            __float2half_rn(v.w - __half2float(hw)));
    }
    // Wout hi/lo split
    for (int j = i; j < H * H; j += stride) {
        float v = Wout[j];
        __half hi = __float2half_rn(v);
        g_Woh[j] = hi;
        g_Wol[j] = __float2half_rn(v - __half2float(hi));
    }
    // combined weights: W[0]=W_in, W[1+r]=W_in@W_rel[r]; biases
    for (int idx = i; idx < 6 * H * H; idx += stride) {
        int m = idx >> 12, k = (idx >> 6) & 63, h = idx & 63;
        float s;
        if (m == 0) {
            s = Win[k * H + h];
            if (k == 0) g_BC[h] = bin[h];
        } else {
            const float* Wr = Wrel + (m - 1) * H * H;
            s = 0.f;
            #pragma unroll 8
            for (int j = 0; j < H; j++) s += Win[k * H + j] * Wr[j * H + h];
            if (k == 0) {
                float sb = 0.f;
                for (int j = 0; j < H; j++) sb += bin[j] * Wr[j * H + h];
                g_BC[m * H + h] = sb;
            }
        }
        g_Wh[idx] = __float2half_rn(s);
    }
    // degrees + per-edge rank within dst group (g_deg/g_cnt pre-zeroed)
    for (int e = i; e < NE; e += stride) {
        atomicAdd(&g_deg[ei[NE + e]], 1);              // col-degree (norm)
        g_rank[e] = atomicAdd(&g_cnt[ei[e]], 1);       // row-degree + rank
    }
}

// ================= tensor-core node GEMM (wmma fp16 split-2) =================
// Grid (391, 6): block = (node-tile of 128, matrix m). 8 warps; warp w owns 16 rows.
// D = Ah@B + Al@B, fp32 accumulate. Fills via cp.async. Output -> g_zy[node][m][lane].
#define LDAB 72      // fp16 leading dim (mult of 8 elems = 16B)
#define LDST 68      // float leading dim for staging
#define TCN_SMEM (2 * 128 * LDAB * 2 + 64 * LDAB * 2)   // 46080 B

__global__ void __launch_bounds__(256) k_node_tc() {
    extern __shared__ char smc[];
    __half* sAh = (__half*)smc;
    __half* sAl = sAh + 128 * LDAB;
    __half* sWh = sAl + 128 * LDAB;
    float*  sSt = (float*)smc;      // staging reuses A region (34.8KB < 36.9KB)

    int t = threadIdx.x;
    int w = t >> 5, lane = t & 31;
    int node0 = blockIdx.x * 128;
    int m = blockIdx.y;

    // A fill via cp.async: 2048 16B chunks (Ah, Al)
    for (int i = t; i < 2048; i += 256) {
        int arr = i >> 10;
        int rc = i & 1023;
        int r = rc >> 3, c8 = rc & 7;
        __half* sdst = (arr ? sAl : sAh) + r * LDAB + c8 * 8;
        if (node0 + r < NN) {
            const __half* gsrc = (arr ? g_Al : g_Ah) + (node0 + r) * 64 + c8 * 8;
            cp16(sdst, gsrc);
        } else {
            *(uint4*)sdst = make_uint4(0, 0, 0, 0);
        }
    }
    // W fill: 512 chunks
    for (int i = t; i < 512; i += 256) {
        int r = i >> 3, c8 = i & 7;
        cp16(sWh + r * LDAB + c8 * 8, g_Wh + m * 4096 + r * 64 + c8 * 8);
    }
    cp_commit_wait();
    __syncthreads();

    wmma::fragment<wmma::accumulator, 16, 16, 16, float> acc[4];
    #pragma unroll
    for (int n = 0; n < 4; n++) wmma::fill_fragment(acc[n], 0.f);

    #pragma unroll
    for (int k = 0; k < 4; k++) {
        wmma::fragment<wmma::matrix_a, 16, 16, 16, __half, wmma::row_major> ah, al;
        wmma::load_matrix_sync(ah, &sAh[(w * 16) * LDAB + k * 16], LDAB);
        wmma::load_matrix_sync(al, &sAl[(w * 16) * LDAB + k * 16], LDAB);
        #pragma unroll
        for (int n = 0; n < 4; n++) {
            wmma::fragment<wmma::matrix_b, 16, 16, 16, __half, wmma::row_major> bh;
            wmma::load_matrix_sync(bh, &sWh[(k * 16) * LDAB + n * 16], LDAB);
            wmma::mma_sync(acc[n], ah, bh, acc[n]);
            wmma::mma_sync(acc[n], al, bh, acc[n]);
        }
    }

    __syncthreads();   // all smem reads (A/W) complete before staging overwrites A
    float* st = sSt + (w * 16) * LDST;   // warp-private 16x68 staging
    #pragma unroll
    for (int n = 0; n < 4; n++)
        wmma::store_matrix_sync(st + n * 16, acc[n], LDST, wmma::mem_row_major);
    __syncwarp();

    for (int i = lane; i < 16 * 16; i += 32) {
        int rr = i >> 4, cgp = i & 15;
        int n = node0 + w * 16 + rr;
        if (n >= NN) continue;
        float4 v = *(float4*)&st[rr * LDST + cgp * 4];
        float4 b = ((const float4*)&g_BC[m * 64])[cgp];
        v.x += b.x; v.y += b.y; v.z += b.z; v.w += b.w;
        if (m == 0) {
            int dg = g_deg[n];
            float dis = dg > 0 ? rsqrtf((float)dg) : 0.f;
            v.x *= dis; v.y *= dis; v.z *= dis; v.w *= dis;
        }
        __half2 h0 = __floats2half2_rn(v.x, v.y);
        __half2 h1 = __floats2half2_rn(v.z, v.w);
        uint2 u = make_uint2(*(unsigned int*)&h0, *(unsigned int*)&h1);
        ((uint2*)g_zy)[(n * 6 + m) * 16 + cgp] = u;
    }
}

// ========== fused scan: chunk sums (warp-parallel) + scan + offsets ==========
__global__ void __launch_bounds__(256) k_scan() {
    __shared__ int csum[256];
    __shared__ int s[256];
    int t = threadIdx.x, w = t >> 5, l = t & 31;

    csum[t] = 0;
    __syncthreads();
    // phase A: each block redundantly computes all NB chunk sums (coalesced)
    for (int c = w; c < NB; c += 8) {
        int sum = 0;
        #pragma unroll
        for (int q = 0; q < 8; q++) {
            int idx = c * 256 + q * 32 + l;
            sum += (idx < NN) ? g_cnt[idx] : 0;
        }
        #pragma unroll
        for (int d = 16; d > 0; d >>= 1) sum += __shfl_down_sync(0xFFFFFFFFu, sum, d);
        if (l == 0) csum[c] = sum;
    }
    __syncthreads();
    // inclusive scan of chunk sums
    #pragma unroll
    for (int d = 1; d < 256; d <<= 1) {
        int u = (t >= d) ? csum[t - d] : 0;
        __syncthreads();
        csum[t] += u;
        __syncthreads();
    }
    // phase B: local scan of this block's chunk
    int b = blockIdx.x;
    int idx = b * 256 + t;
    int v = idx < NN ? g_cnt[idx] : 0;
    s[t] = v;
    __syncthreads();
    #pragma unroll
    for (int d = 1; d < 256; d <<= 1) {
        int u = (t >= d) ? s[t - d] : 0;
        __syncthreads();
        s[t] += u;
        __syncthreads();
    }
    int boff = b > 0 ? csum[b - 1] : 0;
    int excl = s[t] - v + boff;
    if (idx < NN) g_off[idx] = excl;
    if (idx == NN - 1) g_off[NN] = NE;
}

// Atomic-free scatter: pos = off[dst] + precomputed rank. Pure load/store.
__global__ void __launch_bounds__(256) k_scatter(const int* __restrict__ ei,
                                                 const int* __restrict__ et) {
    int base = blockIdx.x * 1024 + threadIdx.x;
    #pragma unroll
    for (int q = 0; q < 4; q++) {
        int e = base + 256 * q;
        if (e < NE) {
            int r  = __ldg(&ei[e]);
            int c  = __ldg(&ei[NE + e]);
            int tp = __ldg(&et[e]);
            int pos = __ldg(&g_off[r]) + __ldg(&g_rank[e]);
            g_es[pos] = c | (tp << 16);
        }
    }
}

// ================= sorted edge pass =================
// One warp per dst node; 4 independent accumulator chains for MLP.
// Gathers from node-major g_zy (z and y of one src node are 768B-local).
__global__ void __launch_bounds__(256) k_edge2() {
    int t = threadIdx.x;
    int node = blockIdx.x * 8 + (t >> 5);
    if (node >= NN) return;
    int l = t & 31;
    int beg = g_off[node], end = g_off[node + 1];

    float2 gcn[4], ss[4], nm[4];
    #pragma unroll
    for (int q = 0; q < 4; q++) {
        gcn[q] = make_float2(0.f, 0.f);
        ss[q]  = make_float2(0.f, 0.f);
        nm[q]  = make_float2(0.f, 0.f);
    }

    int i = beg;
    for (; i + 3 < end; i += 4) {
        int pk[4];
        #pragma unroll
        for (int q = 0; q < 4; q++) pk[q] = __ldg(&g_es[i + q]);
        unsigned int zu[4], yu[4];
        #pragma unroll
        for (int q = 0; q < 4; q++) {
            int c = pk[q] & 0xFFFF, tp = pk[q] >> 16;
            int base6 = c * 192 + l;
            zu[q] = __ldg(&g_zy[base6]);
            yu[q] = __ldg(&g_zy[base6 + (tp + 1) * 32]);
        }
        #pragma unroll
        for (int q = 0; q < 4; q++) {
            float2 zv = __half22float2(*(__half2*)&zu[q]);
            float2 yv = __half22float2(*(__half2*)&yu[q]);
            float ex = __expf(yv.x), ey = __expf(yv.y);
            gcn[q].x += zv.x;       gcn[q].y += zv.y;
            ss[q].x  += ex;         ss[q].y  += ey;
            nm[q].x  += yv.x * ex;  nm[q].y  += yv.y * ey;
        }
    }
    for (; i < end; i++) {
        int pk = __ldg(&g_es[i]);
        int c = pk & 0xFFFF, tp = pk >> 16;
        int base6 = c * 192 + l;
        unsigned int zu = __ldg(&g_zy[base6]);
        unsigned int yu = __ldg(&g_zy[base6 + (tp + 1) * 32]);
        float2 zv = __half22float2(*(__half2*)&zu);
        float2 yv = __half22float2(*(__half2*)&yu);
        float ex = __expf(yv.x), ey = __expf(yv.y);
        gcn[0].x += zv.x;       gcn[0].y += zv.y;
        ss[0].x  += ex;         ss[0].y  += ey;
        nm[0].x  += yv.x * ex;  nm[0].y  += yv.y * ey;
    }

    float2 G = make_float2(gcn[0].x + gcn[1].x + gcn[2].x + gcn[3].x,
                           gcn[0].y + gcn[1].y + gcn[2].y + gcn[3].y);
    float2 S = make_float2(ss[0].x + ss[1].x + ss[2].x + ss[3].x,
                           ss[0].y + ss[1].y + ss[2].y + ss[3].y);
    float2 U = make_float2(nm[0].x + nm[1].x + nm[2].x + nm[3].x,
                           nm[0].y + nm[1].y + nm[2].y + nm[3].y);

    int dg = g_deg[node];
    float dis = dg > 0 ? rsqrtf((float)dg) : 0.f;
    float2 m;
    m.x = dis * G.x + 0.5f * fmaxf(U.x / (S.x + 1e-16f), 0.f);
    m.y = dis * G.y + 0.5f * fmaxf(U.y / (S.y + 1e-16f), 0.f);

    __half2 mh = __floats2half2_rn(m.x, m.y);
    float2 mhf = __half22float2(mh);
    __half2 ml = __floats2half2_rn(m.x - mhf.x, m.y - mhf.y);
    g_mh[node * 32 + l] = *(unsigned int*)&mh;
    g_ml[node * 32 + l] = *(unsigned int*)&ml;
}

// ================= output GEMM (wmma, 3-term split) =================
// Grid 391: 128 nodes/block, 8 warps. D = Mh@Woh + Ml@Woh + Mh@Wol.
// Tail: zero g_deg/g_cnt for the next call (self-restoring state).
#define KOUT_SMEM (2 * 128 * LDAB * 2 + 2 * 64 * LDAB * 2)   // 55296 B

__global__ void __launch_bounds__(256) k_out_tc(const float* __restrict__ bout,
                                                float* __restrict__ out) {
    extern __shared__ char smc[];
    __half* sMh = (__half*)smc;
    __half* sMl = sMh + 128 * LDAB;
    __half* sWh = sMl + 128 * LDAB;
    __half* sWl = sWh + 64 * LDAB;
    float*  sSt = (float*)smc;

    int t = threadIdx.x;
    int w = t >> 5, lane = t & 31;
    int node0 = blockIdx.x * 128;

    for (int i = t; i < 2048; i += 256) {
        int arr = i >> 10;
        int rc = i & 1023;
        int r = rc >> 3, c8 = rc & 7;
        __half* sdst = (arr ? sMl : sMh) + r * LDAB + c8 * 8;
        if (node0 + r < NN) {
            const __half* gsrc = (const __half*)(arr ? g_ml : g_mh) + (node0 + r) * 64 + c8 * 8;
            cp16(sdst, gsrc);
        } else {
            *(uint4*)sdst = make_uint4(0, 0, 0, 0);
        }
    }
    for (int i = t; i < 1024; i += 256) {
        int arr = i >> 9;
        int rc = i & 511;
        int r = rc >> 3, c8 = rc & 7;
        __half* sdst = (arr ? sWl : sWh) + r * LDAB + c8 * 8;
        const __half* gsrc = (arr ? g_Wol : g_Woh) + r * 64 + c8 * 8;
        cp16(sdst, gsrc);
    }

    // tail-zero degree arrays for the next call (overlaps with cp.async)
    int gid = blockIdx.x * 256 + t;
    if (gid < NN) { g_deg[gid] = 0; g_cnt[gid] = 0; }

    cp_commit_wait();
    __syncthreads();

    wmma::fragment<wmma::accumulator, 16, 16, 16, float> acc[4];
    #pragma unroll
    for (int n = 0; n < 4; n++) wmma::fill_fragment(acc[n], 0.f);

    #pragma unroll
    for (int k = 0; k < 4; k++) {
        wmma::fragment<wmma::matrix_a, 16, 16, 16, __half, wmma::row_major> ah, al;
        wmma::load_matrix_sync(ah, &sMh[(w * 16) * LDAB + k * 16], LDAB);
        wmma::load_matrix_sync(al, &sMl[(w * 16) * LDAB + k * 16], LDAB);
        #pragma unroll
        for (int n = 0; n < 4; n++) {
            wmma::fragment<wmma::matrix_b, 16, 16, 16, __half, wmma::row_major> bh, bl;
            wmma::load_matrix_sync(bh, &sWh[(k * 16) * LDAB + n * 16], LDAB);
            wmma::load_matrix_sync(bl, &sWl[(k * 16) * LDAB + n * 16], LDAB);
            wmma::mma_sync(acc[n], ah, bh, acc[n]);
            wmma::mma_sync(acc[n], al, bh, acc[n]);
            wmma::mma_sync(acc[n], ah, bl, acc[n]);
        }
    }

    __syncthreads();
    float* st = sSt + (w * 16) * LDST;
    #pragma unroll
    for (int n = 0; n < 4; n++)
        wmma::store_matrix_sync(st + n * 16, acc[n], LDST, wmma::mem_row_major);
    __syncwarp();

    for (int i = lane; i < 16 * 16; i += 32) {
        int rr = i >> 4, cgp = i & 15;
        int n = node0 + w * 16 + rr;
        if (n >= NN) continue;
        float4 v = *(float4*)&st[rr * LDST + cgp * 4];
        float4 b = __ldg(&((const float4*)bout)[cgp]);
        v.x += b.x; v.y += b.y; v.z += b.z; v.w += b.w;
        ((float4*)out)[n * 16 + cgp] = v;
    }
}

extern "C" void kernel_launch(void* const* d_in, const int* in_sizes, int n_in,
                              void* d_out, int out_size) {
    const float* risk = (const float*)d_in[0];
    // d_in[1] = edge_weight (unused by the reference)
    const float* Win  = (const float*)d_in[2];
    const float* bin  = (const float*)d_in[3];
    const float* Wrel = (const float*)d_in[4];
    const float* Wout = (const float*)d_in[5];
    const float* bout = (const float*)d_in[6];
    const int*   ei   = (const int*)d_in[7];   // [2, NE]: row (dst), col (src)
    const int*   et   = (const int*)d_in[8];
    float* out = (float*)d_out;

    cudaFuncSetAttribute(k_node_tc, cudaFuncAttributeMaxDynamicSharedMemorySize, TCN_SMEM);
    cudaFuncSetAttribute(k_out_tc,  cudaFuncAttributeMaxDynamicSharedMemorySize, KOUT_SMEM);

    // 6 launches; the ncu capture profiles launch #4 = k_scatter this round.
    k_setup<<<512, 256>>>(risk, Wout, Win, bin, Wrel, ei);
    k_node_tc<<<dim3((NN + 127) / 128, 6), 256, TCN_SMEM>>>();
    k_scan<<<NB, 256>>>();
    k_scatter<<<(NE + 1023) / 1024, 256>>>(ei, et);
    k_edge2<<<(NN + 7) / 8, 256>>>();
    k_out_tc<<<(NN + 127) / 128, 256, KOUT_SMEM>>>(bout, out);
}